// round 3
// baseline (speedup 1.0000x reference)
#include <cuda_runtime.h>
#include <math.h>

#define BB 8
#define NN 512
#define FIN 128
#define HH 4
#define CC 64
#define OUTF (2*HH*CC)   // 512

// scratch
__device__ float g_feats[BB*HH*NN*CC];   // [b][h][n][c]
__device__ float g_as[BB*HH*NN];
__device__ float g_an[BB*HH*NN];

// ---------------------------------------------------------------------------
// Kernel 1: feats = X @ kernels (per head), emit relu(feats) to out[:,:, :H*C],
// and a_s/a_n logit dot products.
// Block: 256 threads, tile 64 rows x 64 cols, thread tile 4x4.
// Grid: (N/64, H, B)
// ---------------------------------------------------------------------------
__global__ __launch_bounds__(256)
void proj_kernel(const float* __restrict__ X,
                 const float* __restrict__ kernels,
                 const float* __restrict__ attn_self,
                 const float* __restrict__ attn_neigh,
                 float* __restrict__ out)
{
    const int b  = blockIdx.z;
    const int h  = blockIdx.y;
    const int n0 = blockIdx.x * 64;
    const int t  = threadIdx.x;
    const int tr = t >> 4;    // 0..15 -> rows tr*4..tr*4+3
    const int tc = t & 15;    // 0..15 -> cols tc*4..tc*4+3

    __shared__ float Ks[64*64];   // [f_chunk][c]
    __shared__ float Xs[64*64];   // [row][f_chunk]
    __shared__ float redS[64];
    __shared__ float redN[64];

    float4 acc[4];
    #pragma unroll
    for (int r = 0; r < 4; r++) acc[r] = make_float4(0.f,0.f,0.f,0.f);

    for (int f0 = 0; f0 < FIN; f0 += 64) {
        __syncthreads();
        // load K chunk: kernels[h, f0..f0+63, 0..63] (contiguous 4096 floats)
        {
            const float4* ksrc = (const float4*)(kernels + (size_t)h*FIN*CC + (size_t)f0*CC);
            float4* kdst = (float4*)Ks;
            #pragma unroll
            for (int q = 0; q < 4; q++) kdst[t + q*256] = ksrc[t + q*256];
        }
        // load X chunk: rows n0..n0+63, f0..f0+63
        {
            #pragma unroll
            for (int q = 0; q < 4; q++) {
                int idx = t + q*256;          // 0..1023 float4s
                int r   = idx >> 4;           // row 0..63
                int qd  = idx & 15;           // float4 within row
                const float4* xsrc = (const float4*)(X + ((size_t)b*NN + n0 + r)*FIN + f0);
                ((float4*)Xs)[idx] = xsrc[qd];
            }
        }
        __syncthreads();

        #pragma unroll 4
        for (int f = 0; f < 64; f++) {
            float4 kv = ((const float4*)Ks)[f*16 + tc];
            #pragma unroll
            for (int rr = 0; rr < 4; rr++) {
                float x = Xs[(tr*4 + rr)*64 + f];
                acc[rr].x = fmaf(x, kv.x, acc[rr].x);
                acc[rr].y = fmaf(x, kv.y, acc[rr].y);
                acc[rr].z = fmaf(x, kv.z, acc[rr].z);
                acc[rr].w = fmaf(x, kv.w, acc[rr].w);
            }
        }
    }

    // attn vectors for my 4 c's
    float as0 = attn_self[h*CC + tc*4 + 0], as1 = attn_self[h*CC + tc*4 + 1];
    float as2 = attn_self[h*CC + tc*4 + 2], as3 = attn_self[h*CC + tc*4 + 3];
    float an0 = attn_neigh[h*CC + tc*4 + 0], an1 = attn_neigh[h*CC + tc*4 + 1];
    float an2 = attn_neigh[h*CC + tc*4 + 2], an3 = attn_neigh[h*CC + tc*4 + 3];

    float* fbase = g_feats + (((size_t)b*HH + h)*NN + n0)*CC;

    float ps[4], pn[4];
    #pragma unroll
    for (int rr = 0; rr < 4; rr++) {
        int n = tr*4 + rr;
        float4 v = acc[rr];
        // scratch feats
        ((float4*)(fbase + (size_t)n*CC))[tc] = v;
        // relu(feats) -> output first half
        float4 rv = make_float4(fmaxf(v.x,0.f), fmaxf(v.y,0.f), fmaxf(v.z,0.f), fmaxf(v.w,0.f));
        ((float4*)(out + ((size_t)(b*NN + n0 + n))*OUTF + h*CC))[tc] = rv;
        ps[rr] = v.x*as0 + v.y*as1 + v.z*as2 + v.w*as3;
        pn[rr] = v.x*an0 + v.y*an1 + v.z*an2 + v.w*an3;
    }

    // reduce across the 16 tc-lanes (xor stays within 16-lane groups)
    #pragma unroll
    for (int s = 1; s < 16; s <<= 1) {
        #pragma unroll
        for (int rr = 0; rr < 4; rr++) {
            ps[rr] += __shfl_xor_sync(0xffffffffu, ps[rr], s);
            pn[rr] += __shfl_xor_sync(0xffffffffu, pn[rr], s);
        }
    }
    if (tc == 0) {
        #pragma unroll
        for (int rr = 0; rr < 4; rr++) {
            redS[tr*4 + rr] = ps[rr];
            redN[tr*4 + rr] = pn[rr];
        }
    }
    __syncthreads();
    if (t < 64) {
        size_t idx = ((size_t)b*HH + h)*NN + n0 + t;
        g_as[idx] = redS[t];
        g_an[idx] = redN[t];
    }
}

// ---------------------------------------------------------------------------
// Kernel 2: streaming masked softmax + attn @ feats, fused relu+bias epilogue.
// Block: 256 threads = 32 i-rows x 8 c-groups (8 channels each).
// Grid: (N/32, H, B). J chunk = 128.
// ---------------------------------------------------------------------------
#define IT 32
#define JT 128

__global__ __launch_bounds__(256)
void attn_kernel(const float* __restrict__ A,
                 const float* __restrict__ biases,
                 float* __restrict__ out)
{
    const int b  = blockIdx.z;
    const int h  = blockIdx.y;
    const int i0 = blockIdx.x * IT;
    const int t  = threadIdx.x;
    const int il = t >> 3;   // 0..31 local row
    const int cg = t & 7;    // 0..7 channel group (8 c each)

    __shared__ float fS[JT*CC];   // 32 KB feats chunk [j][c]
    __shared__ float wS[IT*JT];   // 16 KB weights [i][j]

    const size_t bh = (size_t)b*HH + h;
    const float* featsBH = g_feats + bh*NN*CC;
    const float  a_si = g_as[bh*NN + i0 + il];
    const float* Arow = A + ((size_t)b*NN + i0 + il)*NN;
    const float* anBH = g_an + bh*NN;

    float acc[8];
    #pragma unroll
    for (int k = 0; k < 8; k++) acc[k] = 0.f;
    float m = -3.0e38f, l = 0.f;

    for (int j0 = 0; j0 < NN; j0 += JT) {
        // ---- load feats chunk [JT][CC] ----
        {
            const float4* src = (const float4*)(featsBH + (size_t)j0*CC);
            float4* dst = (float4*)fS;
            #pragma unroll
            for (int q = 0; q < 8; q++) dst[t + q*256] = src[t + q*256];
        }
        __syncthreads();

        // ---- logits for my 16 j's ----
        float e[16];
        unsigned msk = 0;
        float cmax = -3.0e38f;
        {
            const float* Aj = Arow + j0 + cg*16;
            const float* anj = anBH + j0 + cg*16;
            #pragma unroll
            for (int k = 0; k < 16; k++) {
                float a = Aj[k];
                float x = a_si + anj[k];
                x = x > 0.f ? x : 0.2f*x;      // LeakyReLU(0.2)
                e[k] = x;
                cmax = fmaxf(cmax, x);
                if (a != 0.f) msk |= (1u << k);
            }
        }
        // max over the 8 lanes sharing this i
        #pragma unroll
        for (int s = 1; s < 8; s <<= 1)
            cmax = fmaxf(cmax, __shfl_xor_sync(0xffffffffu, cmax, s));
        float mnew  = fmaxf(m, cmax);
        float scale = __expf(m - mnew);

        float ls = 0.f;
        float* wrowW = wS + il*JT + cg*16;
        #pragma unroll
        for (int k = 0; k < 16; k++) {
            float w = ((msk >> k) & 1u) ? __expf(e[k] - mnew) : 0.f;
            wrowW[k] = w;
            ls += w;
        }
        #pragma unroll
        for (int s = 1; s < 8; s <<= 1)
            ls += __shfl_xor_sync(0xffffffffu, ls, s);

        l = l*scale + ls;
        m = mnew;
        #pragma unroll
        for (int k = 0; k < 8; k++) acc[k] *= scale;
        __syncthreads();

        // ---- accumulate: acc[c] += w_j * feats[j][c], skip zero weights ----
        {
            const float*  wrow = wS + il*JT;
            const float4* fS4  = (const float4*)fS;
            #pragma unroll 2
            for (int jj = 0; jj < JT; jj++) {
                float w = wrow[jj];
                if (w != 0.f) {
                    float4 f0 = fS4[jj*16 + cg*2];
                    float4 f1 = fS4[jj*16 + cg*2 + 1];
                    acc[0] = fmaf(w, f0.x, acc[0]);
                    acc[1] = fmaf(w, f0.y, acc[1]);
                    acc[2] = fmaf(w, f0.z, acc[2]);
                    acc[3] = fmaf(w, f0.w, acc[3]);
                    acc[4] = fmaf(w, f1.x, acc[4]);
                    acc[5] = fmaf(w, f1.y, acc[5]);
                    acc[6] = fmaf(w, f1.z, acc[6]);
                    acc[7] = fmaf(w, f1.w, acc[7]);
                }
            }
        }
        __syncthreads();
    }

    // epilogue: normalize, +bias, relu (agg simplification: relu(out_h) only)
    float inv = 1.f / l;
    float* o = out + ((size_t)(b*NN + i0 + il))*OUTF + HH*CC + h*CC + cg*8;
    const float* bi = biases + h*CC + cg*8;
    #pragma unroll
    for (int k = 0; k < 8; k++) {
        float v = acc[k]*inv + bi[k];
        o[k] = fmaxf(v, 0.f);
    }
}

extern "C" void kernel_launch(void* const* d_in, const int* in_sizes, int n_in,
                              void* d_out, int out_size)
{
    const float* X          = (const float*)d_in[0];  // [8,512,128]
    const float* A          = (const float*)d_in[1];  // [8,512,512]
    const float* kernels    = (const float*)d_in[2];  // [4,128,64]
    const float* biases     = (const float*)d_in[3];  // [4,64]
    const float* attn_self  = (const float*)d_in[4];  // [4,64]
    const float* attn_neigh = (const float*)d_in[5];  // [4,64]
    float* out = (float*)d_out;                       // [8,512,512]

    proj_kernel<<<dim3(NN/64, HH, BB), 256>>>(X, kernels, attn_self, attn_neigh, out);
    attn_kernel<<<dim3(NN/IT, HH, BB), 256>>>(A, biases, out);
}

// round 4
// speedup vs baseline: 1.0040x; 1.0040x over previous
#include <cuda_runtime.h>
#include <math.h>

#define BB 8
#define NN 512
#define FIN 128
#define HH 4
#define CC 64
#define OUTF (2*HH*CC)   // 512

// scratch
__device__ float g_feats[BB*HH*NN*CC];   // [b][h][n][c]
__device__ float g_as[BB*HH*NN];
__device__ float g_an[BB*HH*NN];

// ---------------------------------------------------------------------------
// Kernel 1: feats = X @ kernels (per head), emit relu(feats) to out[:,:, :H*C],
// and a_s/a_n logit dot products.
// Block: 256 threads, tile 64 rows x 64 cols, thread tile 4x4.
// Grid: (N/64, H, B)
// ---------------------------------------------------------------------------
__global__ __launch_bounds__(256)
void proj_kernel(const float* __restrict__ X,
                 const float* __restrict__ kernels,
                 const float* __restrict__ attn_self,
                 const float* __restrict__ attn_neigh,
                 float* __restrict__ out)
{
    const int b  = blockIdx.z;
    const int h  = blockIdx.y;
    const int n0 = blockIdx.x * 64;
    const int t  = threadIdx.x;
    const int tr = t >> 4;    // 0..15 -> rows tr*4..tr*4+3
    const int tc = t & 15;    // 0..15 -> cols tc*4..tc*4+3

    __shared__ float Ks[64*64];   // [f_chunk][c]
    __shared__ float Xs[64*64];   // [row][f_chunk]
    __shared__ float redS[64];
    __shared__ float redN[64];

    float4 acc[4];
    #pragma unroll
    for (int r = 0; r < 4; r++) acc[r] = make_float4(0.f,0.f,0.f,0.f);

    for (int f0 = 0; f0 < FIN; f0 += 64) {
        __syncthreads();
        // load K chunk: kernels[h, f0..f0+63, 0..63] (contiguous 4096 floats)
        {
            const float4* ksrc = (const float4*)(kernels + (size_t)h*FIN*CC + (size_t)f0*CC);
            float4* kdst = (float4*)Ks;
            #pragma unroll
            for (int q = 0; q < 4; q++) kdst[t + q*256] = ksrc[t + q*256];
        }
        // load X chunk: rows n0..n0+63, f0..f0+63
        {
            #pragma unroll
            for (int q = 0; q < 4; q++) {
                int idx = t + q*256;          // 0..1023 float4s
                int r   = idx >> 4;           // row 0..63
                int qd  = idx & 15;           // float4 within row
                const float4* xsrc = (const float4*)(X + ((size_t)b*NN + n0 + r)*FIN + f0);
                ((float4*)Xs)[idx] = xsrc[qd];
            }
        }
        __syncthreads();

        #pragma unroll 4
        for (int f = 0; f < 64; f++) {
            float4 kv = ((const float4*)Ks)[f*16 + tc];
            #pragma unroll
            for (int rr = 0; rr < 4; rr++) {
                float x = Xs[(tr*4 + rr)*64 + f];
                acc[rr].x = fmaf(x, kv.x, acc[rr].x);
                acc[rr].y = fmaf(x, kv.y, acc[rr].y);
                acc[rr].z = fmaf(x, kv.z, acc[rr].z);
                acc[rr].w = fmaf(x, kv.w, acc[rr].w);
            }
        }
    }

    // attn vectors for my 4 c's
    float as0 = attn_self[h*CC + tc*4 + 0], as1 = attn_self[h*CC + tc*4 + 1];
    float as2 = attn_self[h*CC + tc*4 + 2], as3 = attn_self[h*CC + tc*4 + 3];
    float an0 = attn_neigh[h*CC + tc*4 + 0], an1 = attn_neigh[h*CC + tc*4 + 1];
    float an2 = attn_neigh[h*CC + tc*4 + 2], an3 = attn_neigh[h*CC + tc*4 + 3];

    float* fbase = g_feats + (((size_t)b*HH + h)*NN + n0)*CC;

    float ps[4], pn[4];
    #pragma unroll
    for (int rr = 0; rr < 4; rr++) {
        int n = tr*4 + rr;
        float4 v = acc[rr];
        // scratch feats
        ((float4*)(fbase + (size_t)n*CC))[tc] = v;
        // relu(feats) -> output first half
        float4 rv = make_float4(fmaxf(v.x,0.f), fmaxf(v.y,0.f), fmaxf(v.z,0.f), fmaxf(v.w,0.f));
        ((float4*)(out + ((size_t)(b*NN + n0 + n))*OUTF + h*CC))[tc] = rv;
        ps[rr] = v.x*as0 + v.y*as1 + v.z*as2 + v.w*as3;
        pn[rr] = v.x*an0 + v.y*an1 + v.z*an2 + v.w*an3;
    }

    // reduce across the 16 tc-lanes (xor stays within 16-lane groups)
    #pragma unroll
    for (int s = 1; s < 16; s <<= 1) {
        #pragma unroll
        for (int rr = 0; rr < 4; rr++) {
            ps[rr] += __shfl_xor_sync(0xffffffffu, ps[rr], s);
            pn[rr] += __shfl_xor_sync(0xffffffffu, pn[rr], s);
        }
    }
    if (tc == 0) {
        #pragma unroll
        for (int rr = 0; rr < 4; rr++) {
            redS[tr*4 + rr] = ps[rr];
            redN[tr*4 + rr] = pn[rr];
        }
    }
    __syncthreads();
    if (t < 64) {
        size_t idx = ((size_t)b*HH + h)*NN + n0 + t;
        g_as[idx] = redS[t];
        g_an[idx] = redN[t];
    }
}

// ---------------------------------------------------------------------------
// Kernel 2: streaming masked softmax + attn @ feats, fused relu+bias epilogue.
// Block: 256 threads = 32 i-rows x 8 c-groups (8 channels each).
// Grid: (N/32, H, B). J chunk = 128.
// ---------------------------------------------------------------------------
#define IT 32
#define JT 128

__global__ __launch_bounds__(256)
void attn_kernel(const float* __restrict__ A,
                 const float* __restrict__ biases,
                 float* __restrict__ out)
{
    const int b  = blockIdx.z;
    const int h  = blockIdx.y;
    const int i0 = blockIdx.x * IT;
    const int t  = threadIdx.x;
    const int il = t >> 3;   // 0..31 local row
    const int cg = t & 7;    // 0..7 channel group (8 c each)

    __shared__ float fS[JT*CC];   // 32 KB feats chunk [j][c]
    __shared__ float wS[IT*JT];   // 16 KB weights [i][j]

    const size_t bh = (size_t)b*HH + h;
    const float* featsBH = g_feats + bh*NN*CC;
    const float  a_si = g_as[bh*NN + i0 + il];
    const float* Arow = A + ((size_t)b*NN + i0 + il)*NN;
    const float* anBH = g_an + bh*NN;

    float acc[8];
    #pragma unroll
    for (int k = 0; k < 8; k++) acc[k] = 0.f;
    float m = -3.0e38f, l = 0.f;

    for (int j0 = 0; j0 < NN; j0 += JT) {
        // ---- load feats chunk [JT][CC] ----
        {
            const float4* src = (const float4*)(featsBH + (size_t)j0*CC);
            float4* dst = (float4*)fS;
            #pragma unroll
            for (int q = 0; q < 8; q++) dst[t + q*256] = src[t + q*256];
        }
        __syncthreads();

        // ---- logits for my 16 j's ----
        float e[16];
        unsigned msk = 0;
        float cmax = -3.0e38f;
        {
            const float* Aj = Arow + j0 + cg*16;
            const float* anj = anBH + j0 + cg*16;
            #pragma unroll
            for (int k = 0; k < 16; k++) {
                float a = Aj[k];
                float x = a_si + anj[k];
                x = x > 0.f ? x : 0.2f*x;      // LeakyReLU(0.2)
                e[k] = x;
                cmax = fmaxf(cmax, x);
                if (a != 0.f) msk |= (1u << k);
            }
        }
        // max over the 8 lanes sharing this i
        #pragma unroll
        for (int s = 1; s < 8; s <<= 1)
            cmax = fmaxf(cmax, __shfl_xor_sync(0xffffffffu, cmax, s));
        float mnew  = fmaxf(m, cmax);
        float scale = __expf(m - mnew);

        float ls = 0.f;
        float* wrowW = wS + il*JT + cg*16;
        #pragma unroll
        for (int k = 0; k < 16; k++) {
            float w = ((msk >> k) & 1u) ? __expf(e[k] - mnew) : 0.f;
            wrowW[k] = w;
            ls += w;
        }
        #pragma unroll
        for (int s = 1; s < 8; s <<= 1)
            ls += __shfl_xor_sync(0xffffffffu, ls, s);

        l = l*scale + ls;
        m = mnew;
        #pragma unroll
        for (int k = 0; k < 8; k++) acc[k] *= scale;
        __syncthreads();

        // ---- accumulate: acc[c] += w_j * feats[j][c], skip zero weights ----
        {
            const float*  wrow = wS + il*JT;
            const float4* fS4  = (const float4*)fS;
            #pragma unroll 2
            for (int jj = 0; jj < JT; jj++) {
                float w = wrow[jj];
                if (w != 0.f) {
                    float4 f0 = fS4[jj*16 + cg*2];
                    float4 f1 = fS4[jj*16 + cg*2 + 1];
                    acc[0] = fmaf(w, f0.x, acc[0]);
                    acc[1] = fmaf(w, f0.y, acc[1]);
                    acc[2] = fmaf(w, f0.z, acc[2]);
                    acc[3] = fmaf(w, f0.w, acc[3]);
                    acc[4] = fmaf(w, f1.x, acc[4]);
                    acc[5] = fmaf(w, f1.y, acc[5]);
                    acc[6] = fmaf(w, f1.z, acc[6]);
                    acc[7] = fmaf(w, f1.w, acc[7]);
                }
            }
        }
        __syncthreads();
    }

    // epilogue: normalize, +bias, relu (agg simplification: relu(out_h) only)
    float inv = 1.f / l;
    float* o = out + ((size_t)(b*NN + i0 + il))*OUTF + HH*CC + h*CC + cg*8;
    const float* bi = biases + h*CC + cg*8;
    #pragma unroll
    for (int k = 0; k < 8; k++) {
        float v = acc[k]*inv + bi[k];
        o[k] = fmaxf(v, 0.f);
    }
}

extern "C" void kernel_launch(void* const* d_in, const int* in_sizes, int n_in,
                              void* d_out, int out_size)
{
    const float* X          = (const float*)d_in[0];  // [8,512,128]
    const float* A          = (const float*)d_in[1];  // [8,512,512]
    const float* kernels    = (const float*)d_in[2];  // [4,128,64]
    const float* biases     = (const float*)d_in[3];  // [4,64]
    const float* attn_self  = (const float*)d_in[4];  // [4,64]
    const float* attn_neigh = (const float*)d_in[5];  // [4,64]
    float* out = (float*)d_out;                       // [8,512,512]

    proj_kernel<<<dim3(NN/64, HH, BB), 256>>>(X, kernels, attn_self, attn_neigh, out);
    attn_kernel<<<dim3(NN/IT, HH, BB), 256>>>(A, biases, out);
}